// round 5
// baseline (speedup 1.0000x reference)
#include <cuda_runtime.h>
#include <cuda_fp16.h>
#include <cuda_bf16.h>

// ---- physical constants (double-precision derived, matching reference) ----
#define KEHALF      7.199822675975274f
#define CUTON_F     2.5f
#define CUTOFF_F    7.5f
#define LRCUT_F     10.0f
#define CUTON16_F   2328306.4365386963f
#define CUT_RCONST  0.009999999997526174f
#define CUT_CONST   0.19999999999608f
#define INV_RANGE   0.2f
#define INV_LR2     0.01f
#define TWO_OVER_LR 0.2f

#define MAX_N 102400
#define MAX_M 2048
#define NSLOT 64
#define MAGIC_SHIFT 38

// fallback i-side packed table (q fp32, idx_m) — used only if magic check fails
__device__ float2 d_qm[MAX_N];
// slot-strided scratch: ALL reductions land here via fire-and-forget RED
__device__ float  d_scratch[MAX_M * NSLOT];
// 0 if idx_m[i] == (i*magic)>>38 for all i
__device__ int    d_bad;

__global__ void init_kernel() { d_bad = 0; }

__global__ void prep_kernel(const float* __restrict__ q,
                            const int* __restrict__ idx_m,
                            int N, float* __restrict__ out, int M,
                            unsigned long long magic) {
    int stride = gridDim.x * blockDim.x;
    int tid = blockIdx.x * blockDim.x + threadIdx.x;
    bool ok = true;
    for (int i = tid; i < N; i += stride) {
        int m = idx_m[i];
        d_qm[i] = make_float2(q[i], __int_as_float(m));
        ok &= ((int)(((unsigned long long)i * magic) >> MAGIC_SHIFT) == m);
    }
    if (!ok) atomicOr(&d_bad, 1);
    for (int i = tid; i < M; i += stride) out[i] = 0.0f;
    for (int i = tid; i < MAX_M * NSLOT; i += stride) d_scratch[i] = 0.0f;
}

__device__ __forceinline__ float edge_energy(float x, float y, float z,
                                             float qi, float qj) {
    float s  = fmaf(x, x, fmaf(y, y, z * z));   // d^2
    float rd = rsqrtf(s);                       // 1/d
    float d  = s * rd;                          // d
    float fac = KEHALF * qi * qj;

    float f;
    if (d >= CUTOFF_F) {
        f = 0.0f;
    } else if (d <= CUTON_F) {
        f = 1.0f;
    } else {
        float t = (CUTOFF_F - d) * INV_RANGE;
        float g = __fdividef(1.0f, t) - __fdividef(1.0f, 1.0f - t);
        f = __fdividef(1.0f, 1.0f + __expf(g));
    }

    float d4  = s * s;
    float d8  = d4 * d4;
    float d16 = d8 * d8;
    float p   = exp2f(-0.0625f * __log2f(d16 + CUTON16_F));

    float omf    = 1.0f - f;
    float damped = fmaf(omf * CUT_RCONST, d, p - CUT_CONST);
    float coul   = (d < LRCUT_F) ? (rd + fmaf(d, INV_LR2, -TWO_OVER_LR)) : 0.0f;
    return fac * fmaf(f, damped, omf * coul);
}

// Pipe budget per SM (44.3K edges):
//   L1tex : streams ~20K + i-gather (4B fp32 q) ~44K            = ~64K? -> gathers
//   smem  : staging ~8K + random fp16 LDS (j)  ~10K             = tiny
//   LTS   : 6.55M fire-and-forget RED.F32, 128K spread addrs    = concurrent
__global__ __launch_bounds__(1024, 1)
void energy_kernel(const float4* __restrict__ r4,
                   const float*  __restrict__ q,
                   const int4*   __restrict__ ii4,
                   const int4*   __restrict__ jj4,
                   const float*  __restrict__ r_scalar,
                   const int*    __restrict__ idx_i,
                   const int*    __restrict__ idx_j,
                   int N, int P, unsigned long long magic) {
    extern __shared__ __half qtab[];

    // stage q -> fp16 shared table (coalesced half2)
    const float2* q2  = (const float2*)q;
    __half2*      qt2 = (__half2*)qtab;
    for (int i = threadIdx.x; i < (N >> 1); i += blockDim.x)
        qt2[i] = __float22half2_rn(q2[i]);
    if ((N & 1) && threadIdx.x == 0)
        qtab[N - 1] = __float2half_rn(q[N - 1]);
    __syncthreads();

    const bool fast = (d_bad == 0);   // uniform across grid

    int gwarp = blockIdx.x * (blockDim.x >> 5) + (threadIdx.x >> 5);
    int slot  = gwarp & (NSLOT - 1);

    int gid    = blockIdx.x * blockDim.x + threadIdx.x;
    int stride = gridDim.x * blockDim.x;
    int P4 = P >> 2;

    if (fast) {
        for (int g = gid; g < P4; g += stride) {
            float4 a = __ldcs(&r4[3 * g + 0]);
            float4 b = __ldcs(&r4[3 * g + 1]);
            float4 c = __ldcs(&r4[3 * g + 2]);
            int4 ii = __ldcs(&ii4[g]);
            int4 jj = __ldcs(&jj4[g]);

            // i-side: 4 independent 4B fp32 gathers (L1tex)
            float qi0 = __ldg(&q[ii.x]);
            float qi1 = __ldg(&q[ii.y]);
            float qi2 = __ldg(&q[ii.z]);
            float qi3 = __ldg(&q[ii.w]);
            // molecule bins via verified magic division (pure ALU)
            int m0 = (int)(((unsigned long long)ii.x * magic) >> MAGIC_SHIFT);
            int m1 = (int)(((unsigned long long)ii.y * magic) >> MAGIC_SHIFT);
            int m2 = (int)(((unsigned long long)ii.z * magic) >> MAGIC_SHIFT);
            int m3 = (int)(((unsigned long long)ii.w * magic) >> MAGIC_SHIFT);
            // j-side: smem crossbar (fp16)
            float qj0 = __half2float(qtab[jj.x]);
            float qj1 = __half2float(qtab[jj.y]);
            float qj2 = __half2float(qtab[jj.z]);
            float qj3 = __half2float(qtab[jj.w]);

            float e0 = edge_energy(a.x, a.y, a.z, qi0, qj0);
            float e1 = edge_energy(a.w, b.x, b.y, qi1, qj1);
            float e2 = edge_energy(b.z, b.w, c.x, qi2, qj2);
            float e3 = edge_energy(c.y, c.z, c.w, qi3, qj3);

            // fire-and-forget RED into strided scratch (no return value used)
            atomicAdd(&d_scratch[m0 * NSLOT + slot], e0);
            atomicAdd(&d_scratch[m1 * NSLOT + slot], e1);
            atomicAdd(&d_scratch[m2 * NSLOT + slot], e2);
            atomicAdd(&d_scratch[m3 * NSLOT + slot], e3);
        }
        for (int e = (P4 << 2) + gid; e < P; e += stride) {
            float x = r_scalar[3 * e + 0];
            float y = r_scalar[3 * e + 1];
            float z = r_scalar[3 * e + 2];
            int i = idx_i[e];
            float qi = __ldg(&q[i]);
            int  m  = (int)(((unsigned long long)i * magic) >> MAGIC_SHIFT);
            float qj = __half2float(qtab[idx_j[e]]);
            atomicAdd(&d_scratch[m * NSLOT + slot], edge_energy(x, y, z, qi, qj));
        }
    } else {
        for (int g = gid; g < P4; g += stride) {
            float4 a = __ldcs(&r4[3 * g + 0]);
            float4 b = __ldcs(&r4[3 * g + 1]);
            float4 c = __ldcs(&r4[3 * g + 2]);
            int4 ii = __ldcs(&ii4[g]);
            int4 jj = __ldcs(&jj4[g]);

            float2 p0 = __ldg(&((const float2*)d_qm)[ii.x]);
            float2 p1 = __ldg(&((const float2*)d_qm)[ii.y]);
            float2 p2 = __ldg(&((const float2*)d_qm)[ii.z]);
            float2 p3 = __ldg(&((const float2*)d_qm)[ii.w]);
            float qj0 = __half2float(qtab[jj.x]);
            float qj1 = __half2float(qtab[jj.y]);
            float qj2 = __half2float(qtab[jj.z]);
            float qj3 = __half2float(qtab[jj.w]);

            float e0 = edge_energy(a.x, a.y, a.z, p0.x, qj0);
            float e1 = edge_energy(a.w, b.x, b.y, p1.x, qj1);
            float e2 = edge_energy(b.z, b.w, c.x, p2.x, qj2);
            float e3 = edge_energy(c.y, c.z, c.w, p3.x, qj3);

            atomicAdd(&d_scratch[__float_as_int(p0.y) * NSLOT + slot], e0);
            atomicAdd(&d_scratch[__float_as_int(p1.y) * NSLOT + slot], e1);
            atomicAdd(&d_scratch[__float_as_int(p2.y) * NSLOT + slot], e2);
            atomicAdd(&d_scratch[__float_as_int(p3.y) * NSLOT + slot], e3);
        }
        for (int e = (P4 << 2) + gid; e < P; e += stride) {
            float x = r_scalar[3 * e + 0];
            float y = r_scalar[3 * e + 1];
            float z = r_scalar[3 * e + 2];
            float2 pi = __ldg(&((const float2*)d_qm)[idx_i[e]]);
            float qj  = __half2float(qtab[idx_j[e]]);
            float ev  = edge_energy(x, y, z, pi.x, qj);
            atomicAdd(&d_scratch[__float_as_int(pi.y) * NSLOT + slot], ev);
        }
    }
}

// fold scratch rows into out: one warp per bin, coalesced row read
__global__ __launch_bounds__(256)
void combine_kernel(float* __restrict__ out, int M) {
    int warp = (blockIdx.x * blockDim.x + threadIdx.x) >> 5;
    int lane = threadIdx.x & 31;
    if (warp < M) {
        float s = d_scratch[warp * NSLOT + lane] + d_scratch[warp * NSLOT + 32 + lane];
        #pragma unroll
        for (int off = 16; off > 0; off >>= 1)
            s += __shfl_down_sync(0xffffffffu, s, off);
        if (lane == 0) out[warp] += s;
    }
}

// fallback for shapes outside the smem-table design
__global__ __launch_bounds__(256)
void energy_fallback(const float* __restrict__ r_scalar,
                     const float* __restrict__ q,
                     const int*   __restrict__ idx_i,
                     const int*   __restrict__ idx_j,
                     const int*   __restrict__ idx_m,
                     int P, float* __restrict__ out) {
    int gid    = blockIdx.x * blockDim.x + threadIdx.x;
    int stride = gridDim.x * blockDim.x;
    for (int e = gid; e < P; e += stride) {
        float x = r_scalar[3 * e + 0];
        float y = r_scalar[3 * e + 1];
        float z = r_scalar[3 * e + 2];
        int i = idx_i[e];
        float ev = edge_energy(x, y, z, q[i], q[idx_j[e]]);
        atomicAdd(&out[idx_m[i]], ev);
    }
}

__global__ void zero_out(float* __restrict__ out, int M) {
    int i = blockIdx.x * blockDim.x + threadIdx.x;
    if (i < M) out[i] = 0.0f;
}

extern "C" void kernel_launch(void* const* d_in, const int* in_sizes, int n_in,
                              void* d_out, int out_size) {
    // metadata order: atomic_numbers, q, r_ij, idx_i, idx_j, idx_m, maxm
    const float* q     = (const float*)d_in[1];
    const float* r_ij  = (const float*)d_in[2];
    const int*   idx_i = (const int*)d_in[3];
    const int*   idx_j = (const int*)d_in[4];
    const int*   idx_m = (const int*)d_in[5];
    int N = in_sizes[1];
    int P = in_sizes[3];
    int M = out_size;
    float* out = (float*)d_out;

    if (N > MAX_N || M > MAX_M || N < 2) {
        zero_out<<<(M + 255) / 256, 256>>>(out, M);
        energy_fallback<<<1184, 256>>>(r_ij, q, idx_i, idx_j, idx_m, P, out);
        return;
    }

    // magic divider for atoms-per-molecule (verified exhaustively on device)
    unsigned long long magic = 0;
    if (M > 0 && N % M == 0) {
        unsigned long long apm = (unsigned long long)(N / M);
        magic = ((1ULL << MAGIC_SHIFT) / apm) + 1ULL;
    }

    init_kernel<<<1, 1>>>();
    prep_kernel<<<1024, 256>>>(q, idx_m, N, out, M, magic);

    int sm_count = 148;
    cudaDeviceGetAttribute(&sm_count, cudaDevAttrMultiProcessorCount, 0);

    size_t smem_bytes = (size_t)2 * (size_t)N;   // fp16 q table
    cudaFuncSetAttribute(energy_kernel, cudaFuncAttributeMaxDynamicSharedMemorySize,
                         (int)smem_bytes);

    energy_kernel<<<sm_count, 1024, smem_bytes>>>(
        (const float4*)r_ij, q, (const int4*)idx_i, (const int4*)idx_j,
        r_ij, idx_i, idx_j, N, P, magic);

    combine_kernel<<<(M * 32 + 255) / 256, 256>>>(out, M);
}

// round 6
// speedup vs baseline: 1.9421x; 1.9421x over previous
#include <cuda_runtime.h>
#include <cuda_fp16.h>
#include <cuda_bf16.h>

// ---- physical constants (double-precision derived, matching reference) ----
#define KEHALF      7.199822675975274f
#define CUTON_F     2.5f
#define CUTOFF_F    7.5f
#define LRCUT_F     10.0f
#define CUTON16_F   2328306.4365386963f
#define CUT_RCONST  0.009999999997526174f
#define CUT_CONST   0.19999999999608f
#define INV_RANGE   0.2f
#define INV_LR2     0.01f
#define TWO_OVER_LR 0.2f

#define MAX_N 102400
#define MAX_M 2048
#define NSLOT 64
#define MAGIC_SHIFT 38

// fp16 charge table (200KB): L1D-resident; serves BOTH i- and j-side gathers
__device__ __half d_qh[MAX_N];
// slot-strided flush scratch. Zero at module load; combine_kernel re-zeros
// after reading, so every kernel_launch (incl. graph replays) sees zeros.
__device__ float  d_scratch[MAX_M * NSLOT];
// 0 if idx_m[i] == (i*magic)>>MAGIC_SHIFT for all i (verified exhaustively)
__device__ int    d_bad;

__global__ void prep_kernel(const float* __restrict__ q,
                            const int* __restrict__ idx_m,
                            int N, unsigned long long magic) {
    int stride = gridDim.x * blockDim.x;
    int tid = blockIdx.x * blockDim.x + threadIdx.x;
    if (tid == 0) d_bad = 0;   // safe: verified writers only OR it below
    __threadfence();
    const float2* q2 = (const float2*)q;
    __half2*      h2 = (__half2*)d_qh;
    bool ok = true;
    int N2 = N >> 1;
    for (int i = tid; i < N2; i += stride) {
        h2[i] = __float22half2_rn(q2[i]);
        int i0 = 2 * i, i1 = 2 * i + 1;
        ok &= ((int)(((unsigned long long)i0 * magic) >> MAGIC_SHIFT) == idx_m[i0]);
        ok &= ((int)(((unsigned long long)i1 * magic) >> MAGIC_SHIFT) == idx_m[i1]);
    }
    if ((N & 1) && tid == 0) {
        d_qh[N - 1] = __float2half_rn(q[N - 1]);
        ok &= ((int)(((unsigned long long)(N - 1) * magic) >> MAGIC_SHIFT) == idx_m[N - 1]);
    }
    if (!ok) atomicOr(&d_bad, 1);
}

__device__ __forceinline__ float edge_energy(float x, float y, float z,
                                             float qi, float qj) {
    float s  = fmaf(x, x, fmaf(y, y, z * z));   // d^2
    float rd = rsqrtf(s);                       // 1/d
    float d  = s * rd;                          // d
    float fac = KEHALF * qi * qj;

    float f;
    if (d >= CUTOFF_F) {
        f = 0.0f;
    } else if (d <= CUTON_F) {
        f = 1.0f;
    } else {
        float t = (CUTOFF_F - d) * INV_RANGE;
        float g = __fdividef(1.0f, t) - __fdividef(1.0f, 1.0f - t);
        f = __fdividef(1.0f, 1.0f + __expf(g));
    }

    float d4  = s * s;
    float d8  = d4 * d4;
    float d16 = d8 * d8;
    float p   = exp2f(-0.0625f * __log2f(d16 + CUTON16_F));

    float omf    = 1.0f - f;
    float damped = fmaf(omf * CUT_RCONST, d, p - CUT_CONST);
    float coul   = (d < LRCUT_F) ? (rd + fmaf(d, INV_LR2, -TWO_OVER_LR)) : 0.0f;
    return fac * fmaf(f, damped, omf * coul);
}

// 8KB static smem only -> L1D keeps ~220KB -> fp16 q table is L1-resident.
// tex pipe: 2 random fp16 gathers/edge (L1 hits) + coalesced streams
// smem pipe: spread ATOMS into ymol (2 cyc/lane floor)
__global__ __launch_bounds__(512, 3)
void energy_kernel(const float4* __restrict__ r4,
                   const float*  __restrict__ q,
                   const int4*   __restrict__ ii4,
                   const int4*   __restrict__ jj4,
                   const float*  __restrict__ r_scalar,
                   const int*    __restrict__ idx_i,
                   const int*    __restrict__ idx_j,
                   const int*    __restrict__ idx_m,
                   int P, int M, unsigned long long magic) {
    __shared__ float ymol[MAX_M];
    for (int b = threadIdx.x; b < MAX_M; b += blockDim.x) ymol[b] = 0.0f;
    __syncthreads();

    const bool fast = (d_bad == 0);

    int gid    = blockIdx.x * blockDim.x + threadIdx.x;
    int stride = gridDim.x * blockDim.x;
    int P4 = P >> 2;

    if (fast) {
        for (int g = gid; g < P4; g += stride) {
            float4 a = __ldcs(&r4[3 * g + 0]);
            float4 b = __ldcs(&r4[3 * g + 1]);
            float4 c = __ldcs(&r4[3 * g + 2]);
            int4 ii = __ldcs(&ii4[g]);
            int4 jj = __ldcs(&jj4[g]);

            // 8 independent 2B gathers from the L1-resident fp16 table
            float qi0 = __half2float(d_qh[ii.x]);
            float qi1 = __half2float(d_qh[ii.y]);
            float qi2 = __half2float(d_qh[ii.z]);
            float qi3 = __half2float(d_qh[ii.w]);
            float qj0 = __half2float(d_qh[jj.x]);
            float qj1 = __half2float(d_qh[jj.y]);
            float qj2 = __half2float(d_qh[jj.z]);
            float qj3 = __half2float(d_qh[jj.w]);
            // molecule bins: pure ALU (verified magic division)
            int m0 = (int)(((unsigned long long)ii.x * magic) >> MAGIC_SHIFT);
            int m1 = (int)(((unsigned long long)ii.y * magic) >> MAGIC_SHIFT);
            int m2 = (int)(((unsigned long long)ii.z * magic) >> MAGIC_SHIFT);
            int m3 = (int)(((unsigned long long)ii.w * magic) >> MAGIC_SHIFT);

            float e0 = edge_energy(a.x, a.y, a.z, qi0, qj0);
            float e1 = edge_energy(a.w, b.x, b.y, qi1, qj1);
            float e2 = edge_energy(b.z, b.w, c.x, qi2, qj2);
            float e3 = edge_energy(c.y, c.z, c.w, qi3, qj3);

            atomicAdd(&ymol[m0], e0);
            atomicAdd(&ymol[m1], e1);
            atomicAdd(&ymol[m2], e2);
            atomicAdd(&ymol[m3], e3);
        }
        for (int e = (P4 << 2) + gid; e < P; e += stride) {
            float x = r_scalar[3 * e + 0];
            float y = r_scalar[3 * e + 1];
            float z = r_scalar[3 * e + 2];
            int i = idx_i[e];
            float qi = __half2float(d_qh[i]);
            float qj = __half2float(d_qh[idx_j[e]]);
            int m = (int)(((unsigned long long)i * magic) >> MAGIC_SHIFT);
            atomicAdd(&ymol[m], edge_energy(x, y, z, qi, qj));
        }
    } else {
        // correctness fallback: fp32 q + gathered idx_m
        for (int e = gid; e < P; e += stride) {
            float x = r_scalar[3 * e + 0];
            float y = r_scalar[3 * e + 1];
            float z = r_scalar[3 * e + 2];
            int i = idx_i[e];
            float ev = edge_energy(x, y, z, __ldg(&q[i]), __ldg(&q[idx_j[e]]));
            atomicAdd(&ymol[idx_m[i]], ev);
        }
    }

    // flush block bins into slot-strided scratch (fire-and-forget RED)
    __syncthreads();
    int slot = blockIdx.x & (NSLOT - 1);
    for (int b = threadIdx.x; b < M; b += blockDim.x) {
        float v = ymol[b];
        if (v != 0.0f) atomicAdd(&d_scratch[b * NSLOT + slot], v);
    }
}

// one warp per bin: sum 64 slots, WRITE out (no prior zeroing needed),
// then re-zero the slots so the next kernel_launch/replay starts clean.
__global__ __launch_bounds__(256)
void combine_kernel(float* __restrict__ out, int M) {
    int warp = (blockIdx.x * blockDim.x + threadIdx.x) >> 5;
    int lane = threadIdx.x & 31;
    if (warp < M) {
        float* row = &d_scratch[warp * NSLOT];
        float s = row[lane] + row[32 + lane];
        row[lane] = 0.0f;
        row[32 + lane] = 0.0f;
        #pragma unroll
        for (int off = 16; off > 0; off >>= 1)
            s += __shfl_down_sync(0xffffffffu, s, off);
        if (lane == 0) out[warp] = s;
    }
}

// host-level fallback for shapes outside the design envelope
__global__ __launch_bounds__(256)
void energy_fallback(const float* __restrict__ r_scalar,
                     const float* __restrict__ q,
                     const int*   __restrict__ idx_i,
                     const int*   __restrict__ idx_j,
                     const int*   __restrict__ idx_m,
                     int P, float* __restrict__ out) {
    int gid    = blockIdx.x * blockDim.x + threadIdx.x;
    int stride = gridDim.x * blockDim.x;
    for (int e = gid; e < P; e += stride) {
        float x = r_scalar[3 * e + 0];
        float y = r_scalar[3 * e + 1];
        float z = r_scalar[3 * e + 2];
        int i = idx_i[e];
        float ev = edge_energy(x, y, z, q[i], q[idx_j[e]]);
        atomicAdd(&out[idx_m[i]], ev);
    }
}

__global__ void zero_out(float* __restrict__ out, int M) {
    int i = blockIdx.x * blockDim.x + threadIdx.x;
    if (i < M) out[i] = 0.0f;
}

extern "C" void kernel_launch(void* const* d_in, const int* in_sizes, int n_in,
                              void* d_out, int out_size) {
    // metadata order: atomic_numbers, q, r_ij, idx_i, idx_j, idx_m, maxm
    const float* q     = (const float*)d_in[1];
    const float* r_ij  = (const float*)d_in[2];
    const int*   idx_i = (const int*)d_in[3];
    const int*   idx_j = (const int*)d_in[4];
    const int*   idx_m = (const int*)d_in[5];
    int N = in_sizes[1];
    int P = in_sizes[3];
    int M = out_size;
    float* out = (float*)d_out;

    if (N > MAX_N || M > MAX_M || N < 2 || M < 1) {
        zero_out<<<(M + 255) / 256, 256>>>(out, M);
        energy_fallback<<<1184, 256>>>(r_ij, q, idx_i, idx_j, idx_m, P, out);
        return;
    }

    // magic divider for atoms-per-molecule; verified exhaustively in prep
    unsigned long long magic = 0;
    if (N % M == 0) {
        unsigned long long apm = (unsigned long long)(N / M);
        magic = ((1ULL << MAGIC_SHIFT) / apm) + 1ULL;
    }

    prep_kernel<<<592, 256>>>(q, idx_m, N, magic);

    int sm_count = 148;
    cudaDeviceGetAttribute(&sm_count, cudaDevAttrMultiProcessorCount, 0);
    int blocks = sm_count * 3;   // 3 CTAs/SM @ 512 threads = 48 warps/SM

    energy_kernel<<<blocks, 512>>>(
        (const float4*)r_ij, q, (const int4*)idx_i, (const int4*)idx_j,
        r_ij, idx_i, idx_j, idx_m, P, M, magic);

    combine_kernel<<<(M * 32 + 255) / 256, 256>>>(out, M);
}

// round 7
// speedup vs baseline: 2.0441x; 1.0525x over previous
#include <cuda_runtime.h>
#include <cuda_fp16.h>
#include <cuda_bf16.h>

// ---- physical constants (double-precision derived, matching reference) ----
#define KEHALF      7.199822675975274f
#define CUTON_F     2.5f
#define CUTOFF_F    7.5f
#define LRCUT_F     10.0f
#define CUTON16_F   2328306.4365386963f
#define CUT_RCONST  0.009999999997526174f
#define CUT_CONST   0.19999999999608f
#define INV_RANGE   0.2f
#define INV_LR2     0.01f
#define TWO_OVER_LR 0.2f

#define MAX_N 102400
#define MAX_M 2048
#define NSLOT 64
#define MAGIC_SHIFT 38

// fp16 charge table (200KB): L1D-resident; serves BOTH i- and j-side gathers
__device__ __half d_qh[MAX_N];
// slot-strided flush scratch; zeroed by prep each launch (combine is read-only)
__device__ float  d_scratch[MAX_M * NSLOT];
// monotone failure flag: statically 0, only ever OR'd (no reset -> no race).
// If set, the gathered-index fallback path runs instead (still correct).
__device__ int    d_bad = 0;

__global__ __launch_bounds__(256)
void prep_kernel(const float* __restrict__ q,
                 const int* __restrict__ idx_m,
                 int N, unsigned long long magic) {
    int stride = gridDim.x * blockDim.x;
    int tid = blockIdx.x * blockDim.x + threadIdx.x;

    // vectorized convert + exhaustive magic-division verification
    const float4* q4 = (const float4*)q;
    const int4*   m4 = (const int4*)idx_m;
    uint2*        h4 = (uint2*)d_qh;          // 4 halves = uint2
    bool ok = true;
    int N4 = N >> 2;
    for (int v = tid; v < N4; v += stride) {
        float4 qv = q4[v];
        int4   mv = m4[v];
        __half2 lo = __floats2half2_rn(qv.x, qv.y);
        __half2 hi = __floats2half2_rn(qv.z, qv.w);
        h4[v] = make_uint2(*(unsigned*)&lo, *(unsigned*)&hi);
        int i0 = 4 * v;
        ok &= ((int)(((unsigned long long)(i0 + 0) * magic) >> MAGIC_SHIFT) == mv.x);
        ok &= ((int)(((unsigned long long)(i0 + 1) * magic) >> MAGIC_SHIFT) == mv.y);
        ok &= ((int)(((unsigned long long)(i0 + 2) * magic) >> MAGIC_SHIFT) == mv.z);
        ok &= ((int)(((unsigned long long)(i0 + 3) * magic) >> MAGIC_SHIFT) == mv.w);
    }
    // scalar tail (N % 4)
    for (int i = (N4 << 2) + tid; i < N; i += stride) {
        d_qh[i] = __float2half_rn(q[i]);
        ok &= ((int)(((unsigned long long)i * magic) >> MAGIC_SHIFT) == idx_m[i]);
    }
    if (!ok) atomicOr(&d_bad, 1);

    // zero the flush scratch (float4 stores, spread across the whole grid)
    float4* s4 = (float4*)d_scratch;
    const float4 z = make_float4(0.f, 0.f, 0.f, 0.f);
    for (int v = tid; v < (MAX_M * NSLOT) / 4; v += stride) s4[v] = z;
}

__device__ __forceinline__ float edge_energy(float x, float y, float z,
                                             float qi, float qj) {
    float s  = fmaf(x, x, fmaf(y, y, z * z));   // d^2
    float rd = rsqrtf(s);                       // 1/d
    float d  = s * rd;                          // d
    float fac = KEHALF * qi * qj;

    float f;
    if (d >= CUTOFF_F) {
        f = 0.0f;
    } else if (d <= CUTON_F) {
        f = 1.0f;
    } else {
        float t = (CUTOFF_F - d) * INV_RANGE;
        float g = __fdividef(1.0f, t) - __fdividef(1.0f, 1.0f - t);
        f = __fdividef(1.0f, 1.0f + __expf(g));
    }

    float d4  = s * s;
    float d8  = d4 * d4;
    float d16 = d8 * d8;
    float p   = exp2f(-0.0625f * __log2f(d16 + CUTON16_F));

    float omf    = 1.0f - f;
    float damped = fmaf(omf * CUT_RCONST, d, p - CUT_CONST);
    float coul   = (d < LRCUT_F) ? (rd + fmaf(d, INV_LR2, -TWO_OVER_LR)) : 0.0f;
    return fac * fmaf(f, damped, omf * coul);
}

// 8KB static smem only -> L1D keeps ~220KB -> fp16 q table is L1-resident.
// tex/LSU pipe: 2 random fp16 gathers/edge (L1 hits) + coalesced streams
// smem pipe   : spread ATOMS into ymol (2 cyc/lane floor)
__global__ __launch_bounds__(512, 3)
void energy_kernel(const float4* __restrict__ r4,
                   const float*  __restrict__ q,
                   const int4*   __restrict__ ii4,
                   const int4*   __restrict__ jj4,
                   const float*  __restrict__ r_scalar,
                   const int*    __restrict__ idx_i,
                   const int*    __restrict__ idx_j,
                   const int*    __restrict__ idx_m,
                   int P, int M, unsigned long long magic) {
    __shared__ float ymol[MAX_M];
    for (int b = threadIdx.x; b < MAX_M; b += blockDim.x) ymol[b] = 0.0f;
    __syncthreads();

    const bool fast = (d_bad == 0);

    int gid    = blockIdx.x * blockDim.x + threadIdx.x;
    int stride = gridDim.x * blockDim.x;
    int P4 = P >> 2;

    if (fast) {
        for (int g = gid; g < P4; g += stride) {
            float4 a = __ldcs(&r4[3 * g + 0]);
            float4 b = __ldcs(&r4[3 * g + 1]);
            float4 c = __ldcs(&r4[3 * g + 2]);
            int4 ii = __ldcs(&ii4[g]);
            int4 jj = __ldcs(&jj4[g]);

            // 8 independent 2B gathers from the L1-resident fp16 table
            float qi0 = __half2float(d_qh[ii.x]);
            float qi1 = __half2float(d_qh[ii.y]);
            float qi2 = __half2float(d_qh[ii.z]);
            float qi3 = __half2float(d_qh[ii.w]);
            float qj0 = __half2float(d_qh[jj.x]);
            float qj1 = __half2float(d_qh[jj.y]);
            float qj2 = __half2float(d_qh[jj.z]);
            float qj3 = __half2float(d_qh[jj.w]);
            // molecule bins: pure ALU (verified magic division)
            int m0 = (int)(((unsigned long long)ii.x * magic) >> MAGIC_SHIFT);
            int m1 = (int)(((unsigned long long)ii.y * magic) >> MAGIC_SHIFT);
            int m2 = (int)(((unsigned long long)ii.z * magic) >> MAGIC_SHIFT);
            int m3 = (int)(((unsigned long long)ii.w * magic) >> MAGIC_SHIFT);

            float e0 = edge_energy(a.x, a.y, a.z, qi0, qj0);
            float e1 = edge_energy(a.w, b.x, b.y, qi1, qj1);
            float e2 = edge_energy(b.z, b.w, c.x, qi2, qj2);
            float e3 = edge_energy(c.y, c.z, c.w, qi3, qj3);

            atomicAdd(&ymol[m0], e0);
            atomicAdd(&ymol[m1], e1);
            atomicAdd(&ymol[m2], e2);
            atomicAdd(&ymol[m3], e3);
        }
        for (int e = (P4 << 2) + gid; e < P; e += stride) {
            float x = r_scalar[3 * e + 0];
            float y = r_scalar[3 * e + 1];
            float z = r_scalar[3 * e + 2];
            int i = idx_i[e];
            float qi = __half2float(d_qh[i]);
            float qj = __half2float(d_qh[idx_j[e]]);
            int m = (int)(((unsigned long long)i * magic) >> MAGIC_SHIFT);
            atomicAdd(&ymol[m], edge_energy(x, y, z, qi, qj));
        }
    } else {
        // correctness fallback: fp32 q + gathered idx_m
        for (int e = gid; e < P; e += stride) {
            float x = r_scalar[3 * e + 0];
            float y = r_scalar[3 * e + 1];
            float z = r_scalar[3 * e + 2];
            int i = idx_i[e];
            float ev = edge_energy(x, y, z, __ldg(&q[i]), __ldg(&q[idx_j[e]]));
            atomicAdd(&ymol[idx_m[i]], ev);
        }
    }

    // flush block bins into slot-strided scratch (fire-and-forget RED)
    __syncthreads();
    int slot = blockIdx.x & (NSLOT - 1);
    for (int b = threadIdx.x; b < M; b += blockDim.x) {
        float v = ymol[b];
        if (v != 0.0f) atomicAdd(&d_scratch[b * NSLOT + slot], v);
    }
}

// warp per bin: coalesced float2/lane over the 64-slot row, shfl-reduce,
// WRITE out (out is poisoned; every bin is written). Read-only on scratch.
__global__ __launch_bounds__(256)
void combine_kernel(float* __restrict__ out, int M) {
    int warp = (blockIdx.x * blockDim.x + threadIdx.x) >> 5;
    int lane = threadIdx.x & 31;
    if (warp < M) {
        float2 v = ((const float2*)&d_scratch[warp * NSLOT])[lane];
        float s = v.x + v.y;
        #pragma unroll
        for (int off = 16; off > 0; off >>= 1)
            s += __shfl_down_sync(0xffffffffu, s, off);
        if (lane == 0) out[warp] = s;
    }
}

// host-level fallback for shapes outside the design envelope
__global__ __launch_bounds__(256)
void energy_fallback(const float* __restrict__ r_scalar,
                     const float* __restrict__ q,
                     const int*   __restrict__ idx_i,
                     const int*   __restrict__ idx_j,
                     const int*   __restrict__ idx_m,
                     int P, float* __restrict__ out) {
    int gid    = blockIdx.x * blockDim.x + threadIdx.x;
    int stride = gridDim.x * blockDim.x;
    for (int e = gid; e < P; e += stride) {
        float x = r_scalar[3 * e + 0];
        float y = r_scalar[3 * e + 1];
        float z = r_scalar[3 * e + 2];
        int i = idx_i[e];
        float ev = edge_energy(x, y, z, q[i], q[idx_j[e]]);
        atomicAdd(&out[idx_m[i]], ev);
    }
}

__global__ void zero_out(float* __restrict__ out, int M) {
    int i = blockIdx.x * blockDim.x + threadIdx.x;
    if (i < M) out[i] = 0.0f;
}

extern "C" void kernel_launch(void* const* d_in, const int* in_sizes, int n_in,
                              void* d_out, int out_size) {
    // metadata order: atomic_numbers, q, r_ij, idx_i, idx_j, idx_m, maxm
    const float* q     = (const float*)d_in[1];
    const float* r_ij  = (const float*)d_in[2];
    const int*   idx_i = (const int*)d_in[3];
    const int*   idx_j = (const int*)d_in[4];
    const int*   idx_m = (const int*)d_in[5];
    int N = in_sizes[1];
    int P = in_sizes[3];
    int M = out_size;
    float* out = (float*)d_out;

    if (N > MAX_N || M > MAX_M || N < 2 || M < 1) {
        zero_out<<<(M + 255) / 256, 256>>>(out, M);
        energy_fallback<<<1184, 256>>>(r_ij, q, idx_i, idx_j, idx_m, P, out);
        return;
    }

    // magic divider for atoms-per-molecule; verified exhaustively in prep.
    // If N%M != 0 (or verification fails), d_bad flips and the gathered
    // fallback path inside energy_kernel is used.
    unsigned long long magic = 0;
    if (N % M == 0) {
        unsigned long long apm = (unsigned long long)(N / M);
        magic = ((1ULL << MAGIC_SHIFT) / apm) + 1ULL;
    }

    prep_kernel<<<256, 256>>>(q, idx_m, N, magic);

    int sm_count = 148;
    cudaDeviceGetAttribute(&sm_count, cudaDevAttrMultiProcessorCount, 0);
    int blocks = sm_count * 3;   // 3 CTAs/SM @ 512 threads = 48 warps/SM

    energy_kernel<<<blocks, 512>>>(
        (const float4*)r_ij, q, (const int4*)idx_i, (const int4*)idx_j,
        r_ij, idx_i, idx_j, idx_m, P, M, magic);

    combine_kernel<<<(M * 32 + 255) / 256, 256>>>(out, M);
}